// round 12
// baseline (speedup 1.0000x reference)
#include <cuda_runtime.h>
#include <cuda_fp16.h>
#include <cstdint>

#define EMB   768
#define NHEAD 8
#define HD    96
#define BATCH 2
#define SEQ   4096
#define MROWS (BATCH * SEQ)          // 8192
#define QKVN  (4 * EMB)              // 3072
#define BHTOT (BATCH * NHEAD)        // 16
#define KPTOT (EMB / 2)              // 384 k-pairs

// ---------------- scratch (static device globals; no allocs) ---------------
__device__ uint32_t g_xpk [MROWS * KPTOT * 2];       // x   fp16 (hi,lo), [m][kp]
__device__ uint32_t g_wpk [KPTOT * QKVN * 2];        // w_qkvr fp16 (hi,lo), [kp][n]
__device__ uint32_t g_apk [MROWS * KPTOT * 2];       // att fp16 (hi,lo), [m][kp]
__device__ uint32_t g_wppk[KPTOT * EMB * 2];         // w_proj fp16 (hi,lo), [kp][n]
__device__ uint32_t g_kpk[BHTOT * SEQ * 96];         // K fp16 (hi,lo), [key][kp]
__device__ uint32_t g_vpk[BHTOT * 64 * 3072];        // V fp16 packed per 64-key block
__device__ float g_q[BHTOT * SEQ * HD];
__device__ float g_k[BHTOT * SEQ * HD];
__device__ float g_v[BHTOT * SEQ * HD];
__device__ float g_r[BHTOT * SEQ * HD];
__device__ float g_att[MROWS * EMB];

// ---------------- helpers ---------------------------------------------------
__device__ __forceinline__ void mma16h(float* d,
                                       uint32_t a0, uint32_t a1, uint32_t a2, uint32_t a3,
                                       uint32_t b0, uint32_t b1) {
    asm volatile(
        "mma.sync.aligned.m16n8k16.row.col.f32.f16.f16.f32 "
        "{%0,%1,%2,%3}, {%4,%5,%6,%7}, {%8,%9}, {%0,%1,%2,%3};"
        : "+f"(d[0]), "+f"(d[1]), "+f"(d[2]), "+f"(d[3])
        : "r"(a0), "r"(a1), "r"(a2), "r"(a3), "r"(b0), "r"(b1));
}

__device__ __forceinline__ uint32_t pack_h2(float a, float b) {
    __half2 h = __floats2half2_rn(a, b);
    return *reinterpret_cast<uint32_t*>(&h);
}
__device__ __forceinline__ uint32_t split_h2(float a, float b, uint32_t* lo) {
    __half2 h = __floats2half2_rn(a, b);
    float hx = __half2float(__low2half(h));
    float hy = __half2float(__high2half(h));
    *lo = pack_h2(a - hx, b - hy);
    return *reinterpret_cast<uint32_t*>(&h);
}

__device__ __forceinline__ void cp16w(uint32_t* dst_smem, const uint32_t* src) {
    uint32_t d = (uint32_t)__cvta_generic_to_shared(dst_smem);
    asm volatile("cp.async.cg.shared.global [%0], [%1], 16;\n" :: "r"(d), "l"(src));
}
__device__ __forceinline__ void cp_commit() {
    asm volatile("cp.async.commit_group;\n");
}
template <int N>
__device__ __forceinline__ void cp_wait() {
    asm volatile("cp.async.wait_group %0;\n" :: "n"(N));
}

// ---------------- pack kernels (generic A/B row/col packers) ----------------
// A-style: [m][K] fp32 -> [m][kp] (hi,lo) word pairs
__global__ void pack_a_gen(const float* __restrict__ in, uint32_t* __restrict__ outp,
                           int n4) {
    int i = blockIdx.x * blockDim.x + threadIdx.x;
    if (i >= n4) return;
    float4 v = ((const float4*)in)[i];
    uint32_t l01, l23;
    uint32_t h01 = split_h2(v.x, v.y, &l01);
    uint32_t h23 = split_h2(v.z, v.w, &l23);
    ((uint4*)outp)[i] = make_uint4(h01, l01, h23, l23);
}
// B-style: [K][N] fp32 -> [kp][n] (hi,lo) pairs (rows 2kp,2kp+1 packed)
__global__ void pack_b_gen(const float* __restrict__ in, uint32_t* __restrict__ outp,
                           int N) {
    int u = blockIdx.x * blockDim.x + threadIdx.x;
    int kp = u / (N / 4), n4 = u % (N / 4);
    const float* p = in + (size_t)(2 * kp) * N + n4 * 4;
    float4 a = *(const float4*)(p);
    float4 b = *(const float4*)(p + N);
    uint32_t lx, ly, lz, lw;
    uint32_t hx = split_h2(a.x, b.x, &lx);
    uint32_t hy = split_h2(a.y, b.y, &ly);
    uint32_t hz = split_h2(a.z, b.z, &lz);
    uint32_t hw = split_h2(a.w, b.w, &lw);
    uint4* o = (uint4*)(outp + ((size_t)kp * N + n4 * 4) * 2);
    o[0] = make_uint4(hx, lx, hy, ly);
    o[1] = make_uint4(hz, lz, hw, lw);
}
__global__ void pack_k() {
    int u = blockIdx.x * blockDim.x + threadIdx.x;
    int kidx = u / 24, c4 = u % 24;
    float4 v = *(const float4*)(g_k + (size_t)kidx * HD + c4 * 4);
    uint32_t l01, l23;
    uint32_t h01 = split_h2(v.x, v.y, &l01);
    uint32_t h23 = split_h2(v.z, v.w, &l23);
    ((uint4*)g_kpk)[u] = make_uint4(h01, l01, h23, l23);
}
__global__ void pack_v() {
    int u = blockIdx.x * blockDim.x + threadIdx.x;
    int c4 = u % 24; int t = u / 24;
    int pk = t % 32; int t2 = t / 32;
    int kb = t2 % 64, bh = t2 / 64;
    const float* va = g_v + ((size_t)bh * SEQ + kb * 64 + 2 * pk) * HD + c4 * 4;
    float4 a = *(const float4*)(va);
    float4 b = *(const float4*)(va + HD);
    int j = pk & 7, ks = pk >> 3;
    int kpm  = ks * 4 + (j & 3);
    int slot = (j >= 4) ? 1 : 0;
    uint32_t* vd = g_vpk + ((size_t)(bh * 64 + kb)) * 3072 + kpm * 192 + c4 * 8 + slot;
    vd[0] = pack_h2(a.x, b.x);
    vd[2] = pack_h2(a.y, b.y);
    vd[4] = pack_h2(a.z, b.z);
    vd[6] = pack_h2(a.w, b.w);
}

// ===========================================================================
// Unified compensated-FP16 GEMM, cp.async 4-STAGE pipeline.
// BM=128 BN=128 BK=16 (8 kp), 256 threads (2x4 warps, 64x32 warp tile).
// EPI=0: bias + qkvr scatter (N=QKVN). EPI=1: bias + store (N=EMB).
// Fragment addressing identical to the validated R10/R11 gemm_qkv.
// ===========================================================================
#define FA_ST 16
#define FB_ST 272
#define FA_SZ (128 * FA_ST)    // 2048
#define FB_SZ (8 * FB_ST)      // 2176
#define NSTAGE 4
#define GEMM_SMEM_BYTES ((NSTAGE * FA_SZ + NSTAGE * FB_SZ) * 4)   // 67584

template <int EPI>
__global__ __launch_bounds__(256, 1)
void gemm_f16(const uint32_t* __restrict__ Apk, const uint32_t* __restrict__ Bpk,
              const float* __restrict__ bias, float* __restrict__ out, int N)
{
    extern __shared__ uint32_t smq[];
    uint32_t* sA = smq;                      // [NSTAGE][FA_SZ]
    uint32_t* sB = smq + NSTAGE * FA_SZ;     // [NSTAGE][FB_SZ]

    const int m0 = blockIdx.y * 128;
    const int n0 = blockIdx.x * 128;
    const int tid  = threadIdx.x;
    const int warp = tid >> 5;
    const int lane = tid & 31;
    const int g = lane >> 2, q = lane & 3;
    const int wm0 = (warp >> 2) * 64;
    const int wn0 = (warp & 3) * 32;

    float acc[4][4][4];
#pragma unroll
    for (int i = 0; i < 4; i++)
#pragma unroll
        for (int j = 0; j < 4; j++)
#pragma unroll
            for (int e = 0; e < 4; e++) acc[i][j][e] = 0.f;

    auto issue = [&](int it8, int s) {
        uint32_t* Ad = sA + s * FA_SZ;
        uint32_t* Bd = sB + s * FB_SZ;
        int kp0 = it8 * 8;
#pragma unroll
        for (int it = 0; it < 2; it++) {
            int u = it * 256 + tid;
            int arow = u >> 2, ac = (u & 3) * 4;
            cp16w(Ad + arow * FA_ST + ac,
                  Apk + ((size_t)(m0 + arow) * KPTOT + kp0) * 2 + ac);
            int brow = u >> 6, bc = (u & 63) * 4;
            cp16w(Bd + brow * FB_ST + bc,
                  Bpk + ((size_t)(kp0 + brow) * N + n0) * 2 + bc);
        }
    };

    const int NITER = EMB / 16;              // 48
#pragma unroll
    for (int p = 0; p < NSTAGE - 1; p++) {   // prologue: 3 stages in flight
        issue(p, p);
        cp_commit();
    }

    for (int i = 0; i < NITER; i++) {
        int s = i & (NSTAGE - 1);
        if (i + NSTAGE - 1 < NITER) {
            issue(i + NSTAGE - 1, (i + NSTAGE - 1) & (NSTAGE - 1));
            cp_commit();
            cp_wait<NSTAGE - 1>();           // oldest (stage i) complete
        } else {
            cp_wait<0>();
        }
        __syncthreads();

        const uint32_t* Ah = sA + s * FA_SZ;
        const uint32_t* Bh = sB + s * FB_SZ;

        uint32_t ahi[4][4], alo[4][4];
#pragma unroll
        for (int mt = 0; mt < 4; mt++) {
            int mrow = wm0 + mt * 16 + g;
            uint2 x0 = *(const uint2*)(Ah + mrow * FA_ST + q * 2);
            uint2 x1 = *(const uint2*)(Ah + (mrow + 8) * FA_ST + q * 2);
            uint2 x2 = *(const uint2*)(Ah + mrow * FA_ST + q * 2 + 8);
            uint2 x3 = *(const uint2*)(Ah + (mrow + 8) * FA_ST + q * 2 + 8);
            ahi[mt][0] = x0.x; alo[mt][0] = x0.y;
            ahi[mt][1] = x1.x; alo[mt][1] = x1.y;
            ahi[mt][2] = x2.x; alo[mt][2] = x2.y;
            ahi[mt][3] = x3.x; alo[mt][3] = x3.y;
        }
        uint32_t bhi[4][2], blo[4][2];
#pragma unroll
        for (int nt = 0; nt < 4; nt++) {
            int ncol = wn0 + nt * 8 + g;
            uint2 b0 = *(const uint2*)(Bh + q * FB_ST + ncol * 2);
            uint2 b1 = *(const uint2*)(Bh + (q + 4) * FB_ST + ncol * 2);
            bhi[nt][0] = b0.x; blo[nt][0] = b0.y;
            bhi[nt][1] = b1.x; blo[nt][1] = b1.y;
        }
#pragma unroll
        for (int mt = 0; mt < 4; mt++)
#pragma unroll
            for (int nt = 0; nt < 4; nt++) {
                mma16h(acc[mt][nt], ahi[mt][0], ahi[mt][1], ahi[mt][2], ahi[mt][3],
                       bhi[nt][0], bhi[nt][1]);
                mma16h(acc[mt][nt], alo[mt][0], alo[mt][1], alo[mt][2], alo[mt][3],
                       bhi[nt][0], bhi[nt][1]);
                mma16h(acc[mt][nt], ahi[mt][0], ahi[mt][1], ahi[mt][2], ahi[mt][3],
                       blo[nt][0], blo[nt][1]);
            }
        __syncthreads();
    }

    // epilogue
#pragma unroll
    for (int mt = 0; mt < 4; mt++)
#pragma unroll
        for (int nt = 0; nt < 4; nt++)
#pragma unroll
            for (int e = 0; e < 4; e++) {
                int rowg = m0 + wm0 + mt * 16 + g + ((e >= 2) ? 8 : 0);
                int colg = n0 + wn0 + nt * 8 + 2 * q + (e & 1);
                float val = acc[mt][nt][e] + bias[colg];
                if (EPI == 1) {
                    out[(size_t)rowg * N + colg] = val;
                } else {
                    int b_   = rowg >> 12;
                    int n    = rowg & 4095;
                    int qk   = colg & 3;
                    int rest = colg >> 2;
                    int d    = rest % 96;
                    int h    = rest / 96;
                    size_t dst = ((size_t)(b_ * NHEAD + h) * SEQ + n) * HD + d;
                    float* t = (qk == 0) ? g_q : (qk == 1) ? g_k : (qk == 2) ? g_v : g_r;
                    t[dst] = val;
                }
            }
}

// ===========================================================================
// Flash attention — R11 verbatim (128-thread CTAs, 2/SM, pre-packed K/V).
// ===========================================================================
#define KSTW 104
#define VSTW 208
#define KHL_SZW (64 * KSTW)              // 6656 per stage
#define VP_SZW  (16 * VSTW)              // 3328 per stage
#define PP_SZW  (4 * 32 * 16)            // 2048 (4 warps)
#define ATT_SMEM_WORDS (2 * KHL_SZW + 2 * VP_SZW + PP_SZW)   // 22016
#define ATT_SMEM_BYTES (ATT_SMEM_WORDS * 4)                  // 88064

__global__ __launch_bounds__(128, 2)
void attn_kernel(const float* __restrict__ gq, const float* __restrict__ gr,
                 float* __restrict__ gatt)
{
    extern __shared__ uint32_t smw[];
    uint32_t* Khl = smw;
    uint32_t* Vp  = smw + 2 * KHL_SZW;
    uint32_t* Pp  = smw + 2 * KHL_SZW + 2 * VP_SZW;

    const int tid  = threadIdx.x;
    const int warp = tid >> 5;
    const int lane = tid & 31;
    const int g = lane >> 2, q = lane & 3;
    const int qr0 = warp * 16;
    uint32_t* Pw = Pp + warp * (32 * 16);

    const int bh = blockIdx.y;
    const int qb = blockIdx.x;
    const size_t base = (size_t)bh * SEQ * HD;

    const float* qp = gq + base + (size_t)(qb * 64 + qr0) * HD;
    uint32_t qhi[6][4], qlo[6][4];
#pragma unroll
    for (int ks = 0; ks < 6; ks++) {
#pragma unroll
        for (int e = 0; e < 4; e++) {
            int row = (e & 1) ? g + 8 : g;
            int d0  = ks * 16 + 2 * q + ((e >= 2) ? 8 : 0);
            float2 f = *(const float2*)(qp + (size_t)row * HD + d0);
            qhi[ks][e] = split_h2(f.x, f.y, &qlo[ks][e]);
        }
    }

    auto issue = [&](int kb, int s) {
        const uint32_t* ksrc = g_kpk + ((size_t)bh * SEQ + kb * 64) * 96;
        const uint32_t* vsrc = g_vpk + ((size_t)(bh * 64 + kb)) * 3072;
        uint32_t* Kd = Khl + s * KHL_SZW;
        uint32_t* Vd = Vp + s * VP_SZW;
#pragma unroll
        for (int i = 0; i < 12; i++) {
            int u = i * 128 + tid;
            int row = u / 24, c4 = u % 24;
            cp16w(Kd + row * KSTW + c4 * 4, ksrc + row * 96 + c4 * 4);
        }
#pragma unroll
        for (int i = 0; i < 6; i++) {
            int u = i * 128 + tid;
            int r = u / 48, c = u % 48;
            cp16w(Vd + r * VSTW + c * 4, vsrc + r * 192 + c * 4);
        }
    };

    float o[12][4];
    float m_a = -1e30f, m_b = -1e30f, l_a = 0.f, l_b = 0.f;
#pragma unroll
    for (int nt = 0; nt < 12; nt++)
#pragma unroll
        for (int e = 0; e < 4; e++) o[nt][e] = 0.f;

    issue(0, 0);
    cp_commit();

    const int NKB = SEQ / 64;
    for (int kb = 0; kb < NKB; kb++) {
        int s = kb & 1;
        if (kb + 1 < NKB) {
            issue(kb + 1, s ^ 1);
            cp_commit();
            cp_wait<1>();
        } else {
            cp_wait<0>();
        }
        __syncthreads();

        const uint32_t* Kh = Khl + s * KHL_SZW;
        const uint32_t* Vh = Vp + s * VP_SZW;

        float s_[8][4];
#pragma unroll
        for (int nt = 0; nt < 8; nt++)
#pragma unroll
            for (int e = 0; e < 4; e++) s_[nt][e] = 0.f;

#pragma unroll
        for (int ks = 0; ks < 6; ks++) {
#pragma unroll
            for (int nt = 0; nt < 8; nt++) {
                const uint32_t* kr = Kh + (nt * 8 + g) * KSTW;
                uint2 w0 = *(const uint2*)(kr + (ks * 8 + q) * 2);
                uint2 w1 = *(const uint2*)(kr + (ks * 8 + q + 4) * 2);
                mma16h(s_[nt], qhi[ks][0], qhi[ks][1], qhi[ks][2], qhi[ks][3],
                       w0.x, w1.x);
                mma16h(s_[nt], qlo[ks][0], qlo[ks][1], qlo[ks][2], qlo[ks][3],
                       w0.x, w1.x);
                mma16h(s_[nt], qhi[ks][0], qhi[ks][1], qhi[ks][2], qhi[ks][3],
                       w0.y, w1.y);
            }
        }

        float mx_a = -1e30f, mx_b = -1e30f;
#pragma unroll
        for (int nt = 0; nt < 8; nt++) {
            mx_a = fmaxf(mx_a, fmaxf(s_[nt][0], s_[nt][1]));
            mx_b = fmaxf(mx_b, fmaxf(s_[nt][2], s_[nt][3]));
        }
        mx_a = fmaxf(mx_a, __shfl_xor_sync(0xffffffffu, mx_a, 1));
        mx_a = fmaxf(mx_a, __shfl_xor_sync(0xffffffffu, mx_a, 2));
        mx_b = fmaxf(mx_b, __shfl_xor_sync(0xffffffffu, mx_b, 1));
        mx_b = fmaxf(mx_b, __shfl_xor_sync(0xffffffffu, mx_b, 2));
        float nm_a = fmaxf(m_a, mx_a), nm_b = fmaxf(m_b, mx_b);
        float sc_a = __expf(m_a - nm_a), sc_b = __expf(m_b - nm_b);
        m_a = nm_a; m_b = nm_b;

        float sum_a = 0.f, sum_b = 0.f;
#pragma unroll
        for (int nt = 0; nt < 8; nt++) {
            float p0 = __expf(s_[nt][0] - nm_a);
            float p1 = __expf(s_[nt][1] - nm_a);
            float p2 = __expf(s_[nt][2] - nm_b);
            float p3 = __expf(s_[nt][3] - nm_b);
            sum_a += p0 + p1; sum_b += p2 + p3;
            int cp = nt * 4 + q;
            *(uint2*)(Pw + cp * 16 + g * 2) =
                make_uint2(pack_h2(p0, p1), pack_h2(p2, p3));
        }
        sum_a += __shfl_xor_sync(0xffffffffu, sum_a, 1);
        sum_a += __shfl_xor_sync(0xffffffffu, sum_a, 2);
        sum_b += __shfl_xor_sync(0xffffffffu, sum_b, 1);
        sum_b += __shfl_xor_sync(0xffffffffu, sum_b, 2);
        l_a = l_a * sc_a + sum_a;
        l_b = l_b * sc_b + sum_b;
#pragma unroll
        for (int nt = 0; nt < 12; nt++) {
            o[nt][0] *= sc_a; o[nt][1] *= sc_a;
            o[nt][2] *= sc_b; o[nt][3] *= sc_b;
        }
        __syncwarp();

#pragma unroll
        for (int ks = 0; ks < 4; ks++) {
            uint2 u1 = *(const uint2*)(Pw + (ks * 8 + q) * 16 + g * 2);
            uint2 u2 = *(const uint2*)(Pw + (ks * 8 + q + 4) * 16 + g * 2);
#pragma unroll
            for (int nt = 0; nt < 12; nt++) {
                uint2 v2 = *(const uint2*)(Vh + (ks * 4 + q) * VSTW + (nt * 8 + g) * 2);
                mma16h(o[nt], u1.x, u1.y, u2.x, u2.y, v2.x, v2.y);
            }
        }
        __syncthreads();
    }

    const float inv_sqrt_emb = 0.03608439182435161f;
    const int b_ = bh >> 3, h = bh & 7;
    const float li_a = inv_sqrt_emb / l_a;
    const float li_b = inv_sqrt_emb / l_b;
    const int n_a = qb * 64 + qr0 + g;
    const int n_b = n_a + 8;
#pragma unroll
    for (int nt = 0; nt < 12; nt++) {
        int d = nt * 8 + 2 * q;
        float ra0 = gr[base + (size_t)n_a * HD + d];
        float ra1 = gr[base + (size_t)n_a * HD + d + 1];
        float rb0 = gr[base + (size_t)n_b * HD + d];
        float rb1 = gr[base + (size_t)n_b * HD + d + 1];
        size_t oa = ((size_t)(b_ * SEQ + n_a)) * EMB + h * HD + d;
        size_t ob = ((size_t)(b_ * SEQ + n_b)) * EMB + h * HD + d;
        gatt[oa]     = o[nt][0] * li_a * ra0;
        gatt[oa + 1] = o[nt][1] * li_a * ra1;
        gatt[ob]     = o[nt][2] * li_b * rb0;
        gatt[ob + 1] = o[nt][3] * li_b * rb1;
    }
}

// ===========================================================================
extern "C" void kernel_launch(void* const* d_in, const int* in_sizes, int n_in,
                              void* d_out, int out_size)
{
    const float* x      = (const float*)d_in[0];
    const float* w_qkvr = (const float*)d_in[1];
    const float* b_qkvr = (const float*)d_in[2];
    const float* w_proj = (const float*)d_in[3];
    const float* b_proj = (const float*)d_in[4];
    float* out = (float*)d_out;

    cudaFuncSetAttribute(gemm_f16<0>,
                         cudaFuncAttributeMaxDynamicSharedMemorySize, GEMM_SMEM_BYTES);
    cudaFuncSetAttribute(gemm_f16<1>,
                         cudaFuncAttributeMaxDynamicSharedMemorySize, GEMM_SMEM_BYTES);
    cudaFuncSetAttribute(attn_kernel,
                         cudaFuncAttributeMaxDynamicSharedMemorySize, ATT_SMEM_BYTES);

    float *gq, *gr, *gatt;
    uint32_t *xpk, *wpk, *apk, *wppk;
    cudaGetSymbolAddress((void**)&gq, g_q);
    cudaGetSymbolAddress((void**)&gr, g_r);
    cudaGetSymbolAddress((void**)&gatt, g_att);
    cudaGetSymbolAddress((void**)&xpk, g_xpk);
    cudaGetSymbolAddress((void**)&wpk, g_wpk);
    cudaGetSymbolAddress((void**)&apk, g_apk);
    cudaGetSymbolAddress((void**)&wppk, g_wppk);

    pack_a_gen<<<MROWS * EMB / 4 / 256, 256>>>(x, xpk, MROWS * EMB / 4);
    pack_b_gen<<<KPTOT * (QKVN / 4) / 256, 256>>>(w_qkvr, wpk, QKVN);
    pack_b_gen<<<KPTOT * (EMB / 4) / 256, 256>>>(w_proj, wppk, EMB);

    gemm_f16<0><<<dim3(QKVN / 128, MROWS / 128), 256, GEMM_SMEM_BYTES>>>(
        xpk, wpk, b_qkvr, nullptr, QKVN);

    pack_k<<<BHTOT * SEQ * 24 / 256, 256>>>();
    pack_v<<<BHTOT * 64 * 32 * 24 / 256, 256>>>();

    attn_kernel<<<dim3(SEQ / 64, BHTOT), 128, ATT_SMEM_BYTES>>>(gq, gr, gatt);

    pack_a_gen<<<MROWS * EMB / 4 / 256, 256>>>(gatt, apk, MROWS * EMB / 4);
    gemm_f16<1><<<dim3(EMB / 128, MROWS / 128), 256, GEMM_SMEM_BYTES>>>(
        apk, wppk, b_proj, out, EMB);
}

// round 13
// speedup vs baseline: 1.0442x; 1.0442x over previous
#include <cuda_runtime.h>
#include <cuda_fp16.h>
#include <cstdint>

#define EMB   768
#define NHEAD 8
#define HD    96
#define BATCH 2
#define SEQ   4096
#define MROWS (BATCH * SEQ)          // 8192
#define QKVN  (4 * EMB)              // 3072
#define BHTOT (BATCH * NHEAD)        // 16
#define KPTOT (EMB / 2)              // 384 k-pairs

// ---------------- scratch (static device globals; no allocs) ---------------
__device__ uint32_t g_xpk [MROWS * KPTOT * 2];       // x   fp16 (hi,lo), [m][kp]
__device__ uint32_t g_wpk [KPTOT * QKVN * 2];        // w_qkvr fp16 (hi,lo), [kp][n]
__device__ uint32_t g_apk [MROWS * KPTOT * 2];       // att fp16 (hi,lo), [m][kp]
__device__ uint32_t g_wppk[KPTOT * EMB * 2];         // w_proj fp16 (hi,lo), [kp][n]
__device__ uint32_t g_kpk[BHTOT * SEQ * 96];         // K fp16 (hi,lo), [key][kp]
__device__ uint32_t g_vpk[BHTOT * 64 * 3072];        // V fp16 packed per 64-key block
__device__ float g_q[BHTOT * SEQ * HD];
__device__ float g_k[BHTOT * SEQ * HD];
__device__ float g_v[BHTOT * SEQ * HD];
__device__ float g_r[BHTOT * SEQ * HD];
__device__ float g_att[MROWS * EMB];

// ---------------- helpers ---------------------------------------------------
__device__ __forceinline__ void mma16h(float* d,
                                       uint32_t a0, uint32_t a1, uint32_t a2, uint32_t a3,
                                       uint32_t b0, uint32_t b1) {
    asm volatile(
        "mma.sync.aligned.m16n8k16.row.col.f32.f16.f16.f32 "
        "{%0,%1,%2,%3}, {%4,%5,%6,%7}, {%8,%9}, {%0,%1,%2,%3};"
        : "+f"(d[0]), "+f"(d[1]), "+f"(d[2]), "+f"(d[3])
        : "r"(a0), "r"(a1), "r"(a2), "r"(a3), "r"(b0), "r"(b1));
}

__device__ __forceinline__ uint32_t pack_h2(float a, float b) {
    __half2 h = __floats2half2_rn(a, b);
    return *reinterpret_cast<uint32_t*>(&h);
}
__device__ __forceinline__ uint32_t split_h2(float a, float b, uint32_t* lo) {
    __half2 h = __floats2half2_rn(a, b);
    float hx = __half2float(__low2half(h));
    float hy = __half2float(__high2half(h));
    *lo = pack_h2(a - hx, b - hy);
    return *reinterpret_cast<uint32_t*>(&h);
}

__device__ __forceinline__ void cp16w(uint32_t* dst_smem, const uint32_t* src) {
    uint32_t d = (uint32_t)__cvta_generic_to_shared(dst_smem);
    asm volatile("cp.async.cg.shared.global [%0], [%1], 16;\n" :: "r"(d), "l"(src));
}
__device__ __forceinline__ void cp_commit() {
    asm volatile("cp.async.commit_group;\n");
}
template <int N>
__device__ __forceinline__ void cp_wait() {
    asm volatile("cp.async.wait_group %0;\n" :: "n"(N));
}

// ---------------- pack kernels — R12 verbatim -------------------------------
__global__ void pack_a_gen(const float* __restrict__ in, uint32_t* __restrict__ outp,
                           int n4) {
    int i = blockIdx.x * blockDim.x + threadIdx.x;
    if (i >= n4) return;
    float4 v = ((const float4*)in)[i];
    uint32_t l01, l23;
    uint32_t h01 = split_h2(v.x, v.y, &l01);
    uint32_t h23 = split_h2(v.z, v.w, &l23);
    ((uint4*)outp)[i] = make_uint4(h01, l01, h23, l23);
}
__global__ void pack_b_gen(const float* __restrict__ in, uint32_t* __restrict__ outp,
                           int N) {
    int u = blockIdx.x * blockDim.x + threadIdx.x;
    int kp = u / (N / 4), n4 = u % (N / 4);
    const float* p = in + (size_t)(2 * kp) * N + n4 * 4;
    float4 a = *(const float4*)(p);
    float4 b = *(const float4*)(p + N);
    uint32_t lx, ly, lz, lw;
    uint32_t hx = split_h2(a.x, b.x, &lx);
    uint32_t hy = split_h2(a.y, b.y, &ly);
    uint32_t hz = split_h2(a.z, b.z, &lz);
    uint32_t hw = split_h2(a.w, b.w, &lw);
    uint4* o = (uint4*)(outp + ((size_t)kp * N + n4 * 4) * 2);
    o[0] = make_uint4(hx, lx, hy, ly);
    o[1] = make_uint4(hz, lz, hw, lw);
}
__global__ void pack_k() {
    int u = blockIdx.x * blockDim.x + threadIdx.x;
    int kidx = u / 24, c4 = u % 24;
    float4 v = *(const float4*)(g_k + (size_t)kidx * HD + c4 * 4);
    uint32_t l01, l23;
    uint32_t h01 = split_h2(v.x, v.y, &l01);
    uint32_t h23 = split_h2(v.z, v.w, &l23);
    ((uint4*)g_kpk)[u] = make_uint4(h01, l01, h23, l23);
}
__global__ void pack_v() {
    int u = blockIdx.x * blockDim.x + threadIdx.x;
    int c4 = u % 24; int t = u / 24;
    int pk = t % 32; int t2 = t / 32;
    int kb = t2 % 64, bh = t2 / 64;
    const float* va = g_v + ((size_t)bh * SEQ + kb * 64 + 2 * pk) * HD + c4 * 4;
    float4 a = *(const float4*)(va);
    float4 b = *(const float4*)(va + HD);
    int j = pk & 7, ks = pk >> 3;
    int kpm  = ks * 4 + (j & 3);
    int slot = (j >= 4) ? 1 : 0;
    uint32_t* vd = g_vpk + ((size_t)(bh * 64 + kb)) * 3072 + kpm * 192 + c4 * 8 + slot;
    vd[0] = pack_h2(a.x, b.x);
    vd[2] = pack_h2(a.y, b.y);
    vd[4] = pack_h2(a.z, b.z);
    vd[6] = pack_h2(a.w, b.w);
}

// ===========================================================================
// Unified compensated-FP16 GEMM — 128-thread CTAs, tile 64x128, 2 CTAs/SM,
// cp.async 2-stage.  4 warps side-by-side (wn0 = warp*32); per-warp 64x32
// fragment work bit-identical to R12.  EPI=0: qkvr scatter. EPI=1: store.
// ===========================================================================
#define FA_ST 16
#define FB_ST 272
#define FA_SZ (64 * FA_ST)     // 1024 words/stage
#define FB_SZ (8 * FB_ST)      // 2176 words/stage
#define GEMM_SMEM_BYTES ((2 * FA_SZ + 2 * FB_SZ) * 4)   // 25600

template <int EPI>
__global__ __launch_bounds__(128, 2)
void gemm_f16(const uint32_t* __restrict__ Apk, const uint32_t* __restrict__ Bpk,
              const float* __restrict__ bias, float* __restrict__ out, int N)
{
    extern __shared__ uint32_t smq[];
    uint32_t* sA = smq;                      // [2][FA_SZ]
    uint32_t* sB = smq + 2 * FA_SZ;          // [2][FB_SZ]

    const int m0 = blockIdx.y * 64;
    const int n0 = blockIdx.x * 128;
    const int tid  = threadIdx.x;
    const int warp = tid >> 5;
    const int lane = tid & 31;
    const int g = lane >> 2, q = lane & 3;
    const int wn0 = warp * 32;

    float acc[4][4][4];
#pragma unroll
    for (int i = 0; i < 4; i++)
#pragma unroll
        for (int j = 0; j < 4; j++)
#pragma unroll
            for (int e = 0; e < 4; e++) acc[i][j][e] = 0.f;

    auto issue = [&](int it8, int s) {
        uint32_t* Ad = sA + s * FA_SZ;
        uint32_t* Bd = sB + s * FB_SZ;
        int kp0 = it8 * 8;
        // A: 64 rows x 4 chunks = 256 ; B: 8 rows x 64 chunks = 512
#pragma unroll
        for (int it = 0; it < 2; it++) {             // A chunks
            int u = it * 128 + tid;
            int arow = u >> 2, ac = (u & 3) * 4;
            cp16w(Ad + arow * FA_ST + ac,
                  Apk + ((size_t)(m0 + arow) * KPTOT + kp0) * 2 + ac);
        }
#pragma unroll
        for (int it = 0; it < 4; it++) {             // B chunks
            int u = it * 128 + tid;
            int brow = u >> 6, bc = (u & 63) * 4;
            cp16w(Bd + brow * FB_ST + bc,
                  Bpk + ((size_t)(kp0 + brow) * N + n0) * 2 + bc);
        }
    };

    issue(0, 0);
    cp_commit();

    const int NITER = EMB / 16;                      // 48
    for (int i = 0; i < NITER; i++) {
        int s = i & 1;
        if (i + 1 < NITER) {
            issue(i + 1, s ^ 1);
            cp_commit();
            cp_wait<1>();
        } else {
            cp_wait<0>();
        }
        __syncthreads();

        const uint32_t* Ah = sA + s * FA_SZ;
        const uint32_t* Bh = sB + s * FB_SZ;

        uint32_t ahi[4][4], alo[4][4];
#pragma unroll
        for (int mt = 0; mt < 4; mt++) {
            int mrow = mt * 16 + g;
            uint2 x0 = *(const uint2*)(Ah + mrow * FA_ST + q * 2);
            uint2 x1 = *(const uint2*)(Ah + (mrow + 8) * FA_ST + q * 2);
            uint2 x2 = *(const uint2*)(Ah + mrow * FA_ST + q * 2 + 8);
            uint2 x3 = *(const uint2*)(Ah + (mrow + 8) * FA_ST + q * 2 + 8);
            ahi[mt][0] = x0.x; alo[mt][0] = x0.y;
            ahi[mt][1] = x1.x; alo[mt][1] = x1.y;
            ahi[mt][2] = x2.x; alo[mt][2] = x2.y;
            ahi[mt][3] = x3.x; alo[mt][3] = x3.y;
        }
        uint32_t bhi[4][2], blo[4][2];
#pragma unroll
        for (int nt = 0; nt < 4; nt++) {
            int ncol = wn0 + nt * 8 + g;
            uint2 b0 = *(const uint2*)(Bh + q * FB_ST + ncol * 2);
            uint2 b1 = *(const uint2*)(Bh + (q + 4) * FB_ST + ncol * 2);
            bhi[nt][0] = b0.x; blo[nt][0] = b0.y;
            bhi[nt][1] = b1.x; blo[nt][1] = b1.y;
        }
#pragma unroll
        for (int mt = 0; mt < 4; mt++)
#pragma unroll
            for (int nt = 0; nt < 4; nt++) {
                mma16h(acc[mt][nt], ahi[mt][0], ahi[mt][1], ahi[mt][2], ahi[mt][3],
                       bhi[nt][0], bhi[nt][1]);
                mma16h(acc[mt][nt], alo[mt][0], alo[mt][1], alo[mt][2], alo[mt][3],
                       bhi[nt][0], bhi[nt][1]);
                mma16h(acc[mt][nt], ahi[mt][0], ahi[mt][1], ahi[mt][2], ahi[mt][3],
                       blo[nt][0], blo[nt][1]);
            }
        __syncthreads();
    }

    // epilogue
#pragma unroll
    for (int mt = 0; mt < 4; mt++)
#pragma unroll
        for (int nt = 0; nt < 4; nt++)
#pragma unroll
            for (int e = 0; e < 4; e++) {
                int rowg = m0 + mt * 16 + g + ((e >= 2) ? 8 : 0);
                int colg = n0 + wn0 + nt * 8 + 2 * q + (e & 1);
                float val = acc[mt][nt][e] + bias[colg];
                if (EPI == 1) {
                    out[(size_t)rowg * N + colg] = val;
                } else {
                    int b_   = rowg >> 12;
                    int n    = rowg & 4095;
                    int qk   = colg & 3;
                    int rest = colg >> 2;
                    int d    = rest % 96;
                    int h    = rest / 96;
                    size_t dst = ((size_t)(b_ * NHEAD + h) * SEQ + n) * HD + d;
                    float* t = (qk == 0) ? g_q : (qk == 1) ? g_k : (qk == 2) ? g_v : g_r;
                    t[dst] = val;
                }
            }
}

// ===========================================================================
// Flash attention — R11 verbatim (128-thread CTAs, 2/SM, pre-packed K/V).
// ===========================================================================
#define KSTW 104
#define VSTW 208
#define KHL_SZW (64 * KSTW)
#define VP_SZW  (16 * VSTW)
#define PP_SZW  (4 * 32 * 16)
#define ATT_SMEM_WORDS (2 * KHL_SZW + 2 * VP_SZW + PP_SZW)   // 22016
#define ATT_SMEM_BYTES (ATT_SMEM_WORDS * 4)                  // 88064

__global__ __launch_bounds__(128, 2)
void attn_kernel(const float* __restrict__ gq, const float* __restrict__ gr,
                 float* __restrict__ gatt)
{
    extern __shared__ uint32_t smw[];
    uint32_t* Khl = smw;
    uint32_t* Vp  = smw + 2 * KHL_SZW;
    uint32_t* Pp  = smw + 2 * KHL_SZW + 2 * VP_SZW;

    const int tid  = threadIdx.x;
    const int warp = tid >> 5;
    const int lane = tid & 31;
    const int g = lane >> 2, q = lane & 3;
    const int qr0 = warp * 16;
    uint32_t* Pw = Pp + warp * (32 * 16);

    const int bh = blockIdx.y;
    const int qb = blockIdx.x;
    const size_t base = (size_t)bh * SEQ * HD;

    const float* qp = gq + base + (size_t)(qb * 64 + qr0) * HD;
    uint32_t qhi[6][4], qlo[6][4];
#pragma unroll
    for (int ks = 0; ks < 6; ks++) {
#pragma unroll
        for (int e = 0; e < 4; e++) {
            int row = (e & 1) ? g + 8 : g;
            int d0  = ks * 16 + 2 * q + ((e >= 2) ? 8 : 0);
            float2 f = *(const float2*)(qp + (size_t)row * HD + d0);
            qhi[ks][e] = split_h2(f.x, f.y, &qlo[ks][e]);
        }
    }

    auto issue = [&](int kb, int s) {
        const uint32_t* ksrc = g_kpk + ((size_t)bh * SEQ + kb * 64) * 96;
        const uint32_t* vsrc = g_vpk + ((size_t)(bh * 64 + kb)) * 3072;
        uint32_t* Kd = Khl + s * KHL_SZW;
        uint32_t* Vd = Vp + s * VP_SZW;
#pragma unroll
        for (int i = 0; i < 12; i++) {
            int u = i * 128 + tid;
            int row = u / 24, c4 = u % 24;
            cp16w(Kd + row * KSTW + c4 * 4, ksrc + row * 96 + c4 * 4);
        }
#pragma unroll
        for (int i = 0; i < 6; i++) {
            int u = i * 128 + tid;
            int r = u / 48, c = u % 48;
            cp16w(Vd + r * VSTW + c * 4, vsrc + r * 192 + c * 4);
        }
    };

    float o[12][4];
    float m_a = -1e30f, m_b = -1e30f, l_a = 0.f, l_b = 0.f;
#pragma unroll
    for (int nt = 0; nt < 12; nt++)
#pragma unroll
        for (int e = 0; e < 4; e++) o[nt][e] = 0.f;

    issue(0, 0);
    cp_commit();

    const int NKB = SEQ / 64;
    for (int kb = 0; kb < NKB; kb++) {
        int s = kb & 1;
        if (kb + 1 < NKB) {
            issue(kb + 1, s ^ 1);
            cp_commit();
            cp_wait<1>();
        } else {
            cp_wait<0>();
        }
        __syncthreads();

        const uint32_t* Kh = Khl + s * KHL_SZW;
        const uint32_t* Vh = Vp + s * VP_SZW;

        float s_[8][4];
#pragma unroll
        for (int nt = 0; nt < 8; nt++)
#pragma unroll
            for (int e = 0; e < 4; e++) s_[nt][e] = 0.f;

#pragma unroll
        for (int ks = 0; ks < 6; ks++) {
#pragma unroll
            for (int nt = 0; nt < 8; nt++) {
                const uint32_t* kr = Kh + (nt * 8 + g) * KSTW;
                uint2 w0 = *(const uint2*)(kr + (ks * 8 + q) * 2);
                uint2 w1 = *(const uint2*)(kr + (ks * 8 + q + 4) * 2);
                mma16h(s_[nt], qhi[ks][0], qhi[ks][1], qhi[ks][2], qhi[ks][3],
                       w0.x, w1.x);
                mma16h(s_[nt], qlo[ks][0], qlo[ks][1], qlo[ks][2], qlo[ks][3],
                       w0.x, w1.x);
                mma16h(s_[nt], qhi[ks][0], qhi[ks][1], qhi[ks][2], qhi[ks][3],
                       w0.y, w1.y);
            }
        }

        float mx_a = -1e30f, mx_b = -1e30f;
#pragma unroll
        for (int nt = 0; nt < 8; nt++) {
            mx_a = fmaxf(mx_a, fmaxf(s_[nt][0], s_[nt][1]));
            mx_b = fmaxf(mx_b, fmaxf(s_[nt][2], s_[nt][3]));
        }
        mx_a = fmaxf(mx_a, __shfl_xor_sync(0xffffffffu, mx_a, 1));
        mx_a = fmaxf(mx_a, __shfl_xor_sync(0xffffffffu, mx_a, 2));
        mx_b = fmaxf(mx_b, __shfl_xor_sync(0xffffffffu, mx_b, 1));
        mx_b = fmaxf(mx_b, __shfl_xor_sync(0xffffffffu, mx_b, 2));
        float nm_a = fmaxf(m_a, mx_a), nm_b = fmaxf(m_b, mx_b);
        float sc_a = __expf(m_a - nm_a), sc_b = __expf(m_b - nm_b);
        m_a = nm_a; m_b = nm_b;

        float sum_a = 0.f, sum_b = 0.f;
#pragma unroll
        for (int nt = 0; nt < 8; nt++) {
            float p0 = __expf(s_[nt][0] - nm_a);
            float p1 = __expf(s_[nt][1] - nm_a);
            float p2 = __expf(s_[nt][2] - nm_b);
            float p3 = __expf(s_[nt][3] - nm_b);
            sum_a += p0 + p1; sum_b += p2 + p3;
            int cp = nt * 4 + q;
            *(uint2*)(Pw + cp * 16 + g * 2) =
                make_uint2(pack_h2(p0, p1), pack_h2(p2, p3));
        }
        sum_a += __shfl_xor_sync(0xffffffffu, sum_a, 1);
        sum_a += __shfl_xor_sync(0xffffffffu, sum_a, 2);
        sum_b += __shfl_xor_sync(0xffffffffu, sum_b, 1);
        sum_b += __shfl_xor_sync(0xffffffffu, sum_b, 2);
        l_a = l_a * sc_a + sum_a;
        l_b = l_b * sc_b + sum_b;
#pragma unroll
        for (int nt = 0; nt < 12; nt++) {
            o[nt][0] *= sc_a; o[nt][1] *= sc_a;
            o[nt][2] *= sc_b; o[nt][3] *= sc_b;
        }
        __syncwarp();

#pragma unroll
        for (int ks = 0; ks < 4; ks++) {
            uint2 u1 = *(const uint2*)(Pw + (ks * 8 + q) * 16 + g * 2);
            uint2 u2 = *(const uint2*)(Pw + (ks * 8 + q + 4) * 16 + g * 2);
#pragma unroll
            for (int nt = 0; nt < 12; nt++) {
                uint2 v2 = *(const uint2*)(Vh + (ks * 4 + q) * VSTW + (nt * 8 + g) * 2);
                mma16h(o[nt], u1.x, u1.y, u2.x, u2.y, v2.x, v2.y);
            }
        }
        __syncthreads();
    }

    const float inv_sqrt_emb = 0.03608439182435161f;
    const int b_ = bh >> 3, h = bh & 7;
    const float li_a = inv_sqrt_emb / l_a;
    const float li_b = inv_sqrt_emb / l_b;
    const int n_a = qb * 64 + qr0 + g;
    const int n_b = n_a + 8;
#pragma unroll
    for (int nt = 0; nt < 12; nt++) {
        int d = nt * 8 + 2 * q;
        float ra0 = gr[base + (size_t)n_a * HD + d];
        float ra1 = gr[base + (size_t)n_a * HD + d + 1];
        float rb0 = gr[base + (size_t)n_b * HD + d];
        float rb1 = gr[base + (size_t)n_b * HD + d + 1];
        size_t oa = ((size_t)(b_ * SEQ + n_a)) * EMB + h * HD + d;
        size_t ob = ((size_t)(b_ * SEQ + n_b)) * EMB + h * HD + d;
        gatt[oa]     = o[nt][0] * li_a * ra0;
        gatt[oa + 1] = o[nt][1] * li_a * ra1;
        gatt[ob]     = o[nt][2] * li_b * rb0;
        gatt[ob + 1] = o[nt][3] * li_b * rb1;
    }
}

// ===========================================================================
extern "C" void kernel_launch(void* const* d_in, const int* in_sizes, int n_in,
                              void* d_out, int out_size)
{
    const float* x      = (const float*)d_in[0];
    const float* w_qkvr = (const float*)d_in[1];
    const float* b_qkvr = (const float*)d_in[2];
    const float* w_proj = (const float*)d_in[3];
    const float* b_proj = (const float*)d_in[4];
    float* out = (float*)d_out;

    cudaFuncSetAttribute(gemm_f16<0>,
                         cudaFuncAttributeMaxDynamicSharedMemorySize, GEMM_SMEM_BYTES);
    cudaFuncSetAttribute(gemm_f16<1>,
                         cudaFuncAttributeMaxDynamicSharedMemorySize, GEMM_SMEM_BYTES);
    cudaFuncSetAttribute(attn_kernel,
                         cudaFuncAttributeMaxDynamicSharedMemorySize, ATT_SMEM_BYTES);

    float *gq, *gr, *gatt;
    uint32_t *xpk, *wpk, *apk, *wppk;
    cudaGetSymbolAddress((void**)&gq, g_q);
    cudaGetSymbolAddress((void**)&gr, g_r);
    cudaGetSymbolAddress((void**)&gatt, g_att);
    cudaGetSymbolAddress((void**)&xpk, g_xpk);
    cudaGetSymbolAddress((void**)&wpk, g_wpk);
    cudaGetSymbolAddress((void**)&apk, g_apk);
    cudaGetSymbolAddress((void**)&wppk, g_wppk);

    pack_a_gen<<<MROWS * EMB / 4 / 256, 256>>>(x, xpk, MROWS * EMB / 4);
    pack_b_gen<<<KPTOT * (QKVN / 4) / 256, 256>>>(w_qkvr, wpk, QKVN);
    pack_b_gen<<<KPTOT * (EMB / 4) / 256, 256>>>(w_proj, wppk, EMB);

    gemm_f16<0><<<dim3(QKVN / 128, MROWS / 64), 128, GEMM_SMEM_BYTES>>>(
        xpk, wpk, b_qkvr, nullptr, QKVN);

    pack_k<<<BHTOT * SEQ * 24 / 256, 256>>>();
    pack_v<<<BHTOT * 64 * 32 * 24 / 256, 256>>>();

    attn_kernel<<<dim3(SEQ / 64, BHTOT), 128, ATT_SMEM_BYTES>>>(gq, gr, gatt);

    pack_a_gen<<<MROWS * EMB / 4 / 256, 256>>>(gatt, apk, MROWS * EMB / 4);
    gemm_f16<1><<<dim3(EMB / 128, MROWS / 64), 128, GEMM_SMEM_BYTES>>>(
        apk, wppk, b_proj, out, EMB);
}

// round 16
// speedup vs baseline: 1.0643x; 1.0193x over previous
#include <cuda_runtime.h>
#include <cuda_fp16.h>
#include <cstdint>

#define EMB   768
#define NHEAD 8
#define HD    96
#define BATCH 2
#define SEQ   4096
#define MROWS (BATCH * SEQ)          // 8192
#define QKVN  (4 * EMB)              // 3072
#define BHTOT (BATCH * NHEAD)        // 16
#define KPTOT (EMB / 2)              // 384 k-pairs

// ---------------- scratch (static device globals; no allocs) ---------------
__device__ uint32_t g_xpk [MROWS * KPTOT * 2];       // x   fp16 (hi,lo), [m][kp]
__device__ uint32_t g_wpk [KPTOT * QKVN * 2];        // w_qkvr fp16 (hi,lo), [kp][n]
__device__ uint32_t g_apk [MROWS * KPTOT * 2];       // att fp16 (hi,lo), [m][kp]
__device__ uint32_t g_wppk[KPTOT * EMB * 2];         // w_proj fp16 (hi,lo), [kp][n]
__device__ uint32_t g_kpk[BHTOT * SEQ * 96];         // K fp16 (hi,lo), [key][kp]
__device__ uint32_t g_vpk[BHTOT * 64 * 3072];        // V fp16 packed per 64-key block
__device__ float g_q[BHTOT * SEQ * HD];
__device__ float g_k[BHTOT * SEQ * HD];
__device__ float g_v[BHTOT * SEQ * HD];
__device__ float g_r[BHTOT * SEQ * HD];

// ---------------- helpers ---------------------------------------------------
__device__ __forceinline__ void mma16h(float* d,
                                       uint32_t a0, uint32_t a1, uint32_t a2, uint32_t a3,
                                       uint32_t b0, uint32_t b1) {
    asm volatile(
        "mma.sync.aligned.m16n8k16.row.col.f32.f16.f16.f32 "
        "{%0,%1,%2,%3}, {%4,%5,%6,%7}, {%8,%9}, {%0,%1,%2,%3};"
        : "+f"(d[0]), "+f"(d[1]), "+f"(d[2]), "+f"(d[3])
        : "r"(a0), "r"(a1), "r"(a2), "r"(a3), "r"(b0), "r"(b1));
}

__device__ __forceinline__ uint32_t pack_h2(float a, float b) {
    __half2 h = __floats2half2_rn(a, b);
    return *reinterpret_cast<uint32_t*>(&h);
}
__device__ __forceinline__ uint32_t split_h2(float a, float b, uint32_t* lo) {
    __half2 h = __floats2half2_rn(a, b);
    float hx = __half2float(__low2half(h));
    float hy = __half2float(__high2half(h));
    *lo = pack_h2(a - hx, b - hy);
    return *reinterpret_cast<uint32_t*>(&h);
}

__device__ __forceinline__ void cp16w(uint32_t* dst_smem, const uint32_t* src) {
    uint32_t d = (uint32_t)__cvta_generic_to_shared(dst_smem);
    asm volatile("cp.async.cg.shared.global [%0], [%1], 16;\n" :: "r"(d), "l"(src));
}
__device__ __forceinline__ void cp_commit() {
    asm volatile("cp.async.commit_group;\n");
}
template <int N>
__device__ __forceinline__ void cp_wait() {
    asm volatile("cp.async.wait_group %0;\n" :: "n"(N));
}

// ---------------- pack kernels — R13 verbatim -------------------------------
__global__ void pack_a_gen(const float* __restrict__ in, uint32_t* __restrict__ outp,
                           int n4) {
    int i = blockIdx.x * blockDim.x + threadIdx.x;
    if (i >= n4) return;
    float4 v = ((const float4*)in)[i];
    uint32_t l01, l23;
    uint32_t h01 = split_h2(v.x, v.y, &l01);
    uint32_t h23 = split_h2(v.z, v.w, &l23);
    ((uint4*)outp)[i] = make_uint4(h01, l01, h23, l23);
}
__global__ void pack_b_gen(const float* __restrict__ in, uint32_t* __restrict__ outp,
                           int N) {
    int u = blockIdx.x * blockDim.x + threadIdx.x;
    int kp = u / (N / 4), n4 = u % (N / 4);
    const float* p = in + (size_t)(2 * kp) * N + n4 * 4;
    float4 a = *(const float4*)(p);
    float4 b = *(const float4*)(p + N);
    uint32_t lx, ly, lz, lw;
    uint32_t hx = split_h2(a.x, b.x, &lx);
    uint32_t hy = split_h2(a.y, b.y, &ly);
    uint32_t hz = split_h2(a.z, b.z, &lz);
    uint32_t hw = split_h2(a.w, b.w, &lw);
    uint4* o = (uint4*)(outp + ((size_t)kp * N + n4 * 4) * 2);
    o[0] = make_uint4(hx, lx, hy, ly);
    o[1] = make_uint4(hz, lz, hw, lw);
}
__global__ void pack_k() {
    int u = blockIdx.x * blockDim.x + threadIdx.x;
    int kidx = u / 24, c4 = u % 24;
    float4 v = *(const float4*)(g_k + (size_t)kidx * HD + c4 * 4);
    uint32_t l01, l23;
    uint32_t h01 = split_h2(v.x, v.y, &l01);
    uint32_t h23 = split_h2(v.z, v.w, &l23);
    ((uint4*)g_kpk)[u] = make_uint4(h01, l01, h23, l23);
}
__global__ void pack_v() {
    int u = blockIdx.x * blockDim.x + threadIdx.x;
    int c4 = u % 24; int t = u / 24;
    int pk = t % 32; int t2 = t / 32;
    int kb = t2 % 64, bh = t2 / 64;
    const float* va = g_v + ((size_t)bh * SEQ + kb * 64 + 2 * pk) * HD + c4 * 4;
    float4 a = *(const float4*)(va);
    float4 b = *(const float4*)(va + HD);
    int j = pk & 7, ks = pk >> 3;
    int kpm  = ks * 4 + (j & 3);
    int slot = (j >= 4) ? 1 : 0;
    uint32_t* vd = g_vpk + ((size_t)(bh * 64 + kb)) * 3072 + kpm * 192 + c4 * 8 + slot;
    vd[0] = pack_h2(a.x, b.x);
    vd[2] = pack_h2(a.y, b.y);
    vd[4] = pack_h2(a.z, b.z);
    vd[6] = pack_h2(a.w, b.w);
}

// ===========================================================================
// Unified compensated-FP16 GEMM — R13 VERBATIM (128-thread CTAs, 64x128 tile,
// 2-stage cp.async, dynamic stage index).  EPI=0: qkvr scatter. EPI=1: store.
// ===========================================================================
#define FA_ST 16
#define FB_ST 272
#define FA_SZ (64 * FA_ST)     // 1024 words/stage
#define FB_SZ (8 * FB_ST)      // 2176 words/stage
#define GEMM_SMEM_BYTES ((2 * FA_SZ + 2 * FB_SZ) * 4)   // 25600

template <int EPI>
__global__ __launch_bounds__(128, 2)
void gemm_f16(const uint32_t* __restrict__ Apk, const uint32_t* __restrict__ Bpk,
              const float* __restrict__ bias, float* __restrict__ out, int N)
{
    extern __shared__ uint32_t smq[];
    uint32_t* sA = smq;                      // [2][FA_SZ]
    uint32_t* sB = smq + 2 * FA_SZ;          // [2][FB_SZ]

    const int m0 = blockIdx.y * 64;
    const int n0 = blockIdx.x * 128;
    const int tid  = threadIdx.x;
    const int warp = tid >> 5;
    const int lane = tid & 31;
    const int g = lane >> 2, q = lane & 3;
    const int wn0 = warp * 32;

    float acc[4][4][4];
#pragma unroll
    for (int i = 0; i < 4; i++)
#pragma unroll
        for (int j = 0; j < 4; j++)
#pragma unroll
            for (int e = 0; e < 4; e++) acc[i][j][e] = 0.f;

    auto issue = [&](int it8, int s) {
        uint32_t* Ad = sA + s * FA_SZ;
        uint32_t* Bd = sB + s * FB_SZ;
        int kp0 = it8 * 8;
#pragma unroll
        for (int it = 0; it < 2; it++) {
            int u = it * 128 + tid;
            int arow = u >> 2, ac = (u & 3) * 4;
            cp16w(Ad + arow * FA_ST + ac,
                  Apk + ((size_t)(m0 + arow) * KPTOT + kp0) * 2 + ac);
        }
#pragma unroll
        for (int it = 0; it < 4; it++) {
            int u = it * 128 + tid;
            int brow = u >> 6, bc = (u & 63) * 4;
            cp16w(Bd + brow * FB_ST + bc,
                  Bpk + ((size_t)(kp0 + brow) * N + n0) * 2 + bc);
        }
    };

    issue(0, 0);
    cp_commit();

    const int NITER = EMB / 16;                      // 48
    for (int i = 0; i < NITER; i++) {
        int s = i & 1;
        if (i + 1 < NITER) {
            issue(i + 1, s ^ 1);
            cp_commit();
            cp_wait<1>();
        } else {
            cp_wait<0>();
        }
        __syncthreads();

        const uint32_t* Ah = sA + s * FA_SZ;
        const uint32_t* Bh = sB + s * FB_SZ;

        uint32_t ahi[4][4], alo[4][4];
#pragma unroll
        for (int mt = 0; mt < 4; mt++) {
            int mrow = mt * 16 + g;
            uint2 x0 = *(const uint2*)(Ah + mrow * FA_ST + q * 2);
            uint2 x1 = *(const uint2*)(Ah + (mrow + 8) * FA_ST + q * 2);
            uint2 x2 = *(const uint2*)(Ah + mrow * FA_ST + q * 2 + 8);
            uint2 x3 = *(const uint2*)(Ah + (mrow + 8) * FA_ST + q * 2 + 8);
            ahi[mt][0] = x0.x; alo[mt][0] = x0.y;
            ahi[mt][1] = x1.x; alo[mt][1] = x1.y;
            ahi[mt][2] = x2.x; alo[mt][2] = x2.y;
            ahi[mt][3] = x3.x; alo[mt][3] = x3.y;
        }
        uint32_t bhi[4][2], blo[4][2];
#pragma unroll
        for (int nt = 0; nt < 4; nt++) {
            int ncol = wn0 + nt * 8 + g;
            uint2 b0 = *(const uint2*)(Bh + q * FB_ST + ncol * 2);
            uint2 b1 = *(const uint2*)(Bh + (q + 4) * FB_ST + ncol * 2);
            bhi[nt][0] = b0.x; blo[nt][0] = b0.y;
            bhi[nt][1] = b1.x; blo[nt][1] = b1.y;
        }
#pragma unroll
        for (int mt = 0; mt < 4; mt++)
#pragma unroll
            for (int nt = 0; nt < 4; nt++) {
                mma16h(acc[mt][nt], ahi[mt][0], ahi[mt][1], ahi[mt][2], ahi[mt][3],
                       bhi[nt][0], bhi[nt][1]);
                mma16h(acc[mt][nt], alo[mt][0], alo[mt][1], alo[mt][2], alo[mt][3],
                       bhi[nt][0], bhi[nt][1]);
                mma16h(acc[mt][nt], ahi[mt][0], ahi[mt][1], ahi[mt][2], ahi[mt][3],
                       blo[nt][0], blo[nt][1]);
            }
        __syncthreads();
    }

    // epilogue — R13 verbatim
#pragma unroll
    for (int mt = 0; mt < 4; mt++)
#pragma unroll
        for (int nt = 0; nt < 4; nt++)
#pragma unroll
            for (int e = 0; e < 4; e++) {
                int rowg = m0 + mt * 16 + g + ((e >= 2) ? 8 : 0);
                int colg = n0 + wn0 + nt * 8 + 2 * q + (e & 1);
                float val = acc[mt][nt][e] + bias[colg];
                if (EPI == 1) {
                    out[(size_t)rowg * N + colg] = val;
                } else {
                    int b_   = rowg >> 12;
                    int n    = rowg & 4095;
                    int qk   = colg & 3;
                    int rest = colg >> 2;
                    int d    = rest % 96;
                    int h    = rest / 96;
                    size_t dst = ((size_t)(b_ * NHEAD + h) * SEQ + n) * HD + d;
                    float* t = (qk == 0) ? g_q : (qk == 1) ? g_k : (qk == 2) ? g_v : g_r;
                    t[dst] = val;
                }
            }
}

// ===========================================================================
// Flash attention — R13 mainloop VERBATIM (dynamic stage index); the ONLY
// change vs R13: epilogue writes g_apk (fp16 hi/lo) directly, replacing the
// g_att store + pack_a_gen pass (bit-identical g_apk; g_att deleted).
// ===========================================================================
#define KSTW 104
#define VSTW 208
#define KHL_SZW (64 * KSTW)
#define VP_SZW  (16 * VSTW)
#define PP_SZW  (4 * 32 * 16)
#define ATT_SMEM_WORDS (2 * KHL_SZW + 2 * VP_SZW + PP_SZW)   // 22016
#define ATT_SMEM_BYTES (ATT_SMEM_WORDS * 4)                  // 88064

__global__ __launch_bounds__(128, 2)
void attn_kernel(const float* __restrict__ gq, const float* __restrict__ gr)
{
    extern __shared__ uint32_t smw[];
    uint32_t* Khl = smw;
    uint32_t* Vp  = smw + 2 * KHL_SZW;
    uint32_t* Pp  = smw + 2 * KHL_SZW + 2 * VP_SZW;

    const int tid  = threadIdx.x;
    const int warp = tid >> 5;
    const int lane = tid & 31;
    const int g = lane >> 2, q = lane & 3;
    const int qr0 = warp * 16;
    uint32_t* Pw = Pp + warp * (32 * 16);

    const int bh = blockIdx.y;
    const int qb = blockIdx.x;
    const size_t base = (size_t)bh * SEQ * HD;

    const float* qp = gq + base + (size_t)(qb * 64 + qr0) * HD;
    uint32_t qhi[6][4], qlo[6][4];
#pragma unroll
    for (int ks = 0; ks < 6; ks++) {
#pragma unroll
        for (int e = 0; e < 4; e++) {
            int row = (e & 1) ? g + 8 : g;
            int d0  = ks * 16 + 2 * q + ((e >= 2) ? 8 : 0);
            float2 f = *(const float2*)(qp + (size_t)row * HD + d0);
            qhi[ks][e] = split_h2(f.x, f.y, &qlo[ks][e]);
        }
    }

    auto issue = [&](int kb, int s) {
        const uint32_t* ksrc = g_kpk + ((size_t)bh * SEQ + kb * 64) * 96;
        const uint32_t* vsrc = g_vpk + ((size_t)(bh * 64 + kb)) * 3072;
        uint32_t* Kd = Khl + s * KHL_SZW;
        uint32_t* Vd = Vp + s * VP_SZW;
#pragma unroll
        for (int i = 0; i < 12; i++) {
            int u = i * 128 + tid;
            int row = u / 24, c4 = u % 24;
            cp16w(Kd + row * KSTW + c4 * 4, ksrc + row * 96 + c4 * 4);
        }
#pragma unroll
        for (int i = 0; i < 6; i++) {
            int u = i * 128 + tid;
            int r = u / 48, c = u % 48;
            cp16w(Vd + r * VSTW + c * 4, vsrc + r * 192 + c * 4);
        }
    };

    float o[12][4];
    float m_a = -1e30f, m_b = -1e30f, l_a = 0.f, l_b = 0.f;
#pragma unroll
    for (int nt = 0; nt < 12; nt++)
#pragma unroll
        for (int e = 0; e < 4; e++) o[nt][e] = 0.f;

    issue(0, 0);
    cp_commit();

    const int NKB = SEQ / 64;                    // 64
    for (int kb = 0; kb < NKB; kb++) {
        int s = kb & 1;
        if (kb + 1 < NKB) {
            issue(kb + 1, s ^ 1);
            cp_commit();
            cp_wait<1>();
        } else {
            cp_wait<0>();
        }
        __syncthreads();

        const uint32_t* Kh = Khl + s * KHL_SZW;
        const uint32_t* Vh = Vp + s * VP_SZW;

        float s_[8][4];
#pragma unroll
        for (int nt = 0; nt < 8; nt++)
#pragma unroll
            for (int e = 0; e < 4; e++) s_[nt][e] = 0.f;

#pragma unroll
        for (int ks = 0; ks < 6; ks++) {
#pragma unroll
            for (int nt = 0; nt < 8; nt++) {
                const uint32_t* kr = Kh + (nt * 8 + g) * KSTW;
                uint2 w0 = *(const uint2*)(kr + (ks * 8 + q) * 2);
                uint2 w1 = *(const uint2*)(kr + (ks * 8 + q + 4) * 2);
                mma16h(s_[nt], qhi[ks][0], qhi[ks][1], qhi[ks][2], qhi[ks][3],
                       w0.x, w1.x);
                mma16h(s_[nt], qlo[ks][0], qlo[ks][1], qlo[ks][2], qlo[ks][3],
                       w0.x, w1.x);
                mma16h(s_[nt], qhi[ks][0], qhi[ks][1], qhi[ks][2], qhi[ks][3],
                       w0.y, w1.y);
            }
        }

        float mx_a = -1e30f, mx_b = -1e30f;
#pragma unroll
        for (int nt = 0; nt < 8; nt++) {
            mx_a = fmaxf(mx_a, fmaxf(s_[nt][0], s_[nt][1]));
            mx_b = fmaxf(mx_b, fmaxf(s_[nt][2], s_[nt][3]));
        }
        mx_a = fmaxf(mx_a, __shfl_xor_sync(0xffffffffu, mx_a, 1));
        mx_a = fmaxf(mx_a, __shfl_xor_sync(0xffffffffu, mx_a, 2));
        mx_b = fmaxf(mx_b, __shfl_xor_sync(0xffffffffu, mx_b, 1));
        mx_b = fmaxf(mx_b, __shfl_xor_sync(0xffffffffu, mx_b, 2));
        float nm_a = fmaxf(m_a, mx_a), nm_b = fmaxf(m_b, mx_b);
        float sc_a = __expf(m_a - nm_a), sc_b = __expf(m_b - nm_b);
        m_a = nm_a; m_b = nm_b;

        float sum_a = 0.f, sum_b = 0.f;
#pragma unroll
        for (int nt = 0; nt < 8; nt++) {
            float p0 = __expf(s_[nt][0] - nm_a);
            float p1 = __expf(s_[nt][1] - nm_a);
            float p2 = __expf(s_[nt][2] - nm_b);
            float p3 = __expf(s_[nt][3] - nm_b);
            sum_a += p0 + p1; sum_b += p2 + p3;
            int cp = nt * 4 + q;
            *(uint2*)(Pw + cp * 16 + g * 2) =
                make_uint2(pack_h2(p0, p1), pack_h2(p2, p3));
        }
        sum_a += __shfl_xor_sync(0xffffffffu, sum_a, 1);
        sum_a += __shfl_xor_sync(0xffffffffu, sum_a, 2);
        sum_b += __shfl_xor_sync(0xffffffffu, sum_b, 1);
        sum_b += __shfl_xor_sync(0xffffffffu, sum_b, 2);
        l_a = l_a * sc_a + sum_a;
        l_b = l_b * sc_b + sum_b;
#pragma unroll
        for (int nt = 0; nt < 12; nt++) {
            o[nt][0] *= sc_a; o[nt][1] *= sc_a;
            o[nt][2] *= sc_b; o[nt][3] *= sc_b;
        }
        __syncwarp();

#pragma unroll
        for (int ks = 0; ks < 4; ks++) {
            uint2 u1 = *(const uint2*)(Pw + (ks * 8 + q) * 16 + g * 2);
            uint2 u2 = *(const uint2*)(Pw + (ks * 8 + q + 4) * 16 + g * 2);
#pragma unroll
            for (int nt = 0; nt < 12; nt++) {
                uint2 v2 = *(const uint2*)(Vh + (ks * 4 + q) * VSTW + (nt * 8 + g) * 2);
                mma16h(o[nt], u1.x, u1.y, u2.x, u2.y, v2.x, v2.y);
            }
        }
        __syncthreads();
    }

    // ---- epilogue: /l, *1/sqrt(768), gate r, split->g_apk directly ----
    const float inv_sqrt_emb = 0.03608439182435161f;
    const int b_ = bh >> 3, h = bh & 7;
    const float li_a = inv_sqrt_emb / l_a;
    const float li_b = inv_sqrt_emb / l_b;
    const int n_a = qb * 64 + qr0 + g;
    const int n_b = n_a + 8;
    const size_t m_a_row = (size_t)(b_ * SEQ + n_a) * KPTOT;
    const size_t m_b_row = (size_t)(b_ * SEQ + n_b) * KPTOT;
#pragma unroll
    for (int nt = 0; nt < 12; nt++) {
        int d = nt * 8 + 2 * q;
        int kp = (h * HD + d) >> 1;              // d even -> exact kp
        float ra0 = gr[base + (size_t)n_a * HD + d];
        float ra1 = gr[base + (size_t)n_a * HD + d + 1];
        float rb0 = gr[base + (size_t)n_b * HD + d];
        float rb1 = gr[base + (size_t)n_b * HD + d + 1];
        float va0 = o[nt][0] * li_a * ra0;
        float va1 = o[nt][1] * li_a * ra1;
        float vb0 = o[nt][2] * li_b * rb0;
        float vb1 = o[nt][3] * li_b * rb1;
        uint32_t loa, lob;
        uint32_t hia = split_h2(va0, va1, &loa);
        uint32_t hib = split_h2(vb0, vb1, &lob);
        *(uint2*)(g_apk + (m_a_row + kp) * 2) = make_uint2(hia, loa);
        *(uint2*)(g_apk + (m_b_row + kp) * 2) = make_uint2(hib, lob);
    }
}

// ===========================================================================
extern "C" void kernel_launch(void* const* d_in, const int* in_sizes, int n_in,
                              void* d_out, int out_size)
{
    const float* x      = (const float*)d_in[0];
    const float* w_qkvr = (const float*)d_in[1];
    const float* b_qkvr = (const float*)d_in[2];
    const float* w_proj = (const float*)d_in[3];
    const float* b_proj = (const float*)d_in[4];
    float* out = (float*)d_out;

    cudaFuncSetAttribute(gemm_f16<0>,
                         cudaFuncAttributeMaxDynamicSharedMemorySize, GEMM_SMEM_BYTES);
    cudaFuncSetAttribute(gemm_f16<1>,
                         cudaFuncAttributeMaxDynamicSharedMemorySize, GEMM_SMEM_BYTES);
    cudaFuncSetAttribute(attn_kernel,
                         cudaFuncAttributeMaxDynamicSharedMemorySize, ATT_SMEM_BYTES);

    float *gq, *gr;
    uint32_t *xpk, *wpk, *apk, *wppk;
    cudaGetSymbolAddress((void**)&gq, g_q);
    cudaGetSymbolAddress((void**)&gr, g_r);
    cudaGetSymbolAddress((void**)&xpk, g_xpk);
    cudaGetSymbolAddress((void**)&wpk, g_wpk);
    cudaGetSymbolAddress((void**)&apk, g_apk);
    cudaGetSymbolAddress((void**)&wppk, g_wppk);

    pack_a_gen<<<MROWS * EMB / 4 / 256, 256>>>(x, xpk, MROWS * EMB / 4);
    pack_b_gen<<<KPTOT * (QKVN / 4) / 256, 256>>>(w_qkvr, wpk, QKVN);
    pack_b_gen<<<KPTOT * (EMB / 4) / 256, 256>>>(w_proj, wppk, EMB);

    gemm_f16<0><<<dim3(QKVN / 128, MROWS / 64), 128, GEMM_SMEM_BYTES>>>(
        xpk, wpk, b_qkvr, nullptr, QKVN);

    pack_k<<<BHTOT * SEQ * 24 / 256, 256>>>();
    pack_v<<<BHTOT * 64 * 32 * 24 / 256, 256>>>();

    attn_kernel<<<dim3(SEQ / 64, BHTOT), 128, ATT_SMEM_BYTES>>>(gq, gr);

    gemm_f16<1><<<dim3(EMB / 128, MROWS / 64), 128, GEMM_SMEM_BYTES>>>(
        apk, wppk, b_proj, out, EMB);
}